// round 1
// baseline (speedup 1.0000x reference)
#include <cuda_runtime.h>
#include <math.h>

// Problem dims (fixed)
#define BB   16
#define SS   2048
#define DD   512
#define HH   512
#define MM   (BB * SS)    // 32768 rows
#define N3H  1536         // 3*H
#define OUTC 1024         // 2*H

// Scratch (allocation-free rule: __device__ globals)
__device__ float g_ZFO_f[MM * N3H];   // 192 MiB
__device__ float g_ZFO_b[MM * N3H];   // 192 MiB
__device__ float g_Y1[MM * OUTC];     // 128 MiB

// ---------------------------------------------------------------------------
// Fused GEMM + bias + activation:
//   C[M, 1536] = act( A[M,K] @ W[K,1536] + bias )
//   cols [0,512): tanh (Z), cols [512,1536): sigmoid (F, O)
// 128x128 tile, BK=16, 256 threads, 8x8 per thread.
// M=32768, N=1536, K in {512,1024}: all tile-aligned, no bounds checks.
// ---------------------------------------------------------------------------
template <int K>
__global__ __launch_bounds__(256) void gemm_act_kernel(
    const float* __restrict__ A,
    const float* __restrict__ W,
    const float* __restrict__ bias,
    float* __restrict__ C)
{
    __shared__ float As[16][128];   // transposed A tile: As[k][m]
    __shared__ float Ws[16][128];   // Ws[k][n]

    const int tid = threadIdx.x;
    const int tx  = tid & 15;       // 0..15  -> 8 cols each
    const int ty  = tid >> 4;       // 0..15  -> 8 rows each
    const int blockM = blockIdx.y * 128;
    const int blockN = blockIdx.x * 128;

    float acc[8][8];
#pragma unroll
    for (int i = 0; i < 8; i++)
#pragma unroll
        for (int j = 0; j < 8; j++) acc[i][j] = 0.0f;

    for (int k0 = 0; k0 < K; k0 += 16) {
        // Load A tile (128 rows x 16 cols) -> transposed into As
#pragma unroll
        for (int it = 0; it < 2; it++) {
            int qq = tid + it * 256;          // 0..511 float4 slots
            int r  = qq >> 2;                 // row within tile
            int c4 = qq & 3;                  // which float4 in the row
            const float4 v = *(const float4*)&A[(size_t)(blockM + r) * K + k0 + c4 * 4];
            As[c4 * 4 + 0][r] = v.x;
            As[c4 * 4 + 1][r] = v.y;
            As[c4 * 4 + 2][r] = v.z;
            As[c4 * 4 + 3][r] = v.w;
        }
        // Load W tile (16 rows x 128 cols)
#pragma unroll
        for (int it = 0; it < 2; it++) {
            int qq = tid + it * 256;
            int r  = qq >> 5;                 // k-row within tile
            int c  = (qq & 31) * 4;           // col within tile
            const float4 v = *(const float4*)&W[(size_t)(k0 + r) * N3H + blockN + c];
            *(float4*)&Ws[r][c] = v;
        }
        __syncthreads();

#pragma unroll
        for (int k = 0; k < 16; k++) {
            float4 a0 = *(const float4*)&As[k][ty * 8];
            float4 a1 = *(const float4*)&As[k][ty * 8 + 4];
            float4 b0 = *(const float4*)&Ws[k][tx * 8];
            float4 b1 = *(const float4*)&Ws[k][tx * 8 + 4];
            float av[8] = {a0.x, a0.y, a0.z, a0.w, a1.x, a1.y, a1.z, a1.w};
            float bv[8] = {b0.x, b0.y, b0.z, b0.w, b1.x, b1.y, b1.z, b1.w};
#pragma unroll
            for (int i = 0; i < 8; i++)
#pragma unroll
                for (int j = 0; j < 8; j++)
                    acc[i][j] = fmaf(av[i], bv[j], acc[i][j]);
        }
        __syncthreads();
    }

    // Epilogue: bias + activation + store
    const int colBase = blockN + tx * 8;
#pragma unroll
    for (int i = 0; i < 8; i++) {
        const int row = blockM + ty * 8 + i;
        float out[8];
#pragma unroll
        for (int j = 0; j < 8; j++) {
            const int col = colBase + j;
            float v = acc[i][j] + bias[col];
            if (col < HH) {
                v = tanhf(v);                          // Z
            } else {
                v = 1.0f / (1.0f + __expf(-v));        // F, O
            }
            out[j] = v;
        }
        float* cptr = &C[(size_t)row * N3H + colBase];
        *(float4*)&cptr[0] = make_float4(out[0], out[1], out[2], out[3]);
        *(float4*)&cptr[4] = make_float4(out[4], out[5], out[6], out[7]);
    }
}

// ---------------------------------------------------------------------------
// fo-pooling scan, both directions in one launch.
// One thread per (dir, b, h): 2*16*512 = 16384 threads.
// ZFO buffers hold ACTIVATED z (tanh), f, o (sigmoid), layout [B*S, 1536].
// Output Y layout [B, S, 1024] with fw in cols [0,512), bw in [512,1024).
// Chunked loads (CH=8 -> 24 independent loads) to hide DRAM latency on the
// serial dependence chain.
// ---------------------------------------------------------------------------
__global__ __launch_bounds__(256) void scan_kernel(
    const float* __restrict__ ZFOf,
    const float* __restrict__ ZFOb,
    float* __restrict__ Y)
{
    const int t   = blockIdx.x * blockDim.x + threadIdx.x;  // 0..16383
    const int dir = t >> 13;          // 0 fw, 1 bw
    const int b   = (t >> 9) & 15;
    const int h   = t & 511;

    const float* __restrict__ Z = dir ? ZFOb : ZFOf;
    const size_t rowBase = (size_t)b * SS;
    const int outOff = dir * HH + h;

    float c = 0.0f;
    constexpr int CH = 8;
    for (int sc = 0; sc < SS; sc += CH) {
        float zv[CH], fv[CH], ov[CH];
#pragma unroll
        for (int j = 0; j < CH; j++) {
            const int s = dir ? (SS - 1 - (sc + j)) : (sc + j);
            const size_t idx = (rowBase + s) * N3H + h;
            zv[j] = Z[idx];
            fv[j] = Z[idx + 512];
            ov[j] = Z[idx + 1024];
        }
#pragma unroll
        for (int j = 0; j < CH; j++) {
            c = fv[j] * c + (1.0f - fv[j]) * zv[j];
            const int s = dir ? (SS - 1 - (sc + j)) : (sc + j);
            Y[(rowBase + s) * OUTC + outOff] = ov[j] * c;
        }
    }
}

// ---------------------------------------------------------------------------
extern "C" void kernel_launch(void* const* d_in, const int* in_sizes, int n_in,
                              void* d_out, int out_size)
{
    const float* X     = (const float*)d_in[0];
    // d_in[1] = seqlens (unused, per reference)
    const float* W_fw0 = (const float*)d_in[2];
    const float* b_fw0 = (const float*)d_in[3];
    const float* W_bw0 = (const float*)d_in[4];
    const float* b_bw0 = (const float*)d_in[5];
    const float* W_fw1 = (const float*)d_in[6];
    const float* b_fw1 = (const float*)d_in[7];
    const float* W_bw1 = (const float*)d_in[8];
    const float* b_bw1 = (const float*)d_in[9];
    float* out = (float*)d_out;

    float *ZFOf, *ZFOb, *Y1;
    cudaGetSymbolAddress((void**)&ZFOf, g_ZFO_f);
    cudaGetSymbolAddress((void**)&ZFOb, g_ZFO_b);
    cudaGetSymbolAddress((void**)&Y1,  g_Y1);

    dim3 gemmGrid(N3H / 128, MM / 128);   // 12 x 256
    dim3 gemmBlock(256);
    dim3 scanGrid(16384 / 256);
    dim3 scanBlock(256);

    // Layer 0: X [B,S,512] (row (b,s) works as GEMM M-row; scan handles order)
    gemm_act_kernel<DD><<<gemmGrid, gemmBlock>>>(X, W_fw0, b_fw0, ZFOf);
    gemm_act_kernel<DD><<<gemmGrid, gemmBlock>>>(X, W_bw0, b_bw0, ZFOb);
    scan_kernel<<<scanGrid, scanBlock>>>(ZFOf, ZFOb, Y1);

    // Layer 1: Y1 [B,S,1024]
    gemm_act_kernel<OUTC><<<gemmGrid, gemmBlock>>>(Y1, W_fw1, b_fw1, ZFOf);
    gemm_act_kernel<OUTC><<<gemmGrid, gemmBlock>>>(Y1, W_bw1, b_bw1, ZFOb);
    scan_kernel<<<scanGrid, scanBlock>>>(ZFOf, ZFOb, out);
}

// round 2
// speedup vs baseline: 2.0902x; 2.0902x over previous
#include <cuda_runtime.h>
#include <math.h>
#include <stdint.h>

// Problem dims (fixed)
#define BB   16
#define SS   2048
#define DD   512
#define HH   512
#define MM   (BB * SS)    // 32768 rows
#define N3H  1536         // 3*H
#define OUTC 1024         // 2*H

#define BM 128
#define BN 128
#define BK 32

// Scratch (allocation-free rule: __device__ globals)
__device__ float g_ZFO_f[MM * N3H];          // 192 MiB (activated z,f,o fwd)
__device__ float g_ZFO_b[MM * N3H];          // 192 MiB (activated z,f,o bwd)
__device__ float g_Y1[MM * OUTC];            // 128 MiB (layer-1 output, tf32 bits)
__device__ float g_Xc[MM * DD];              // 64 MiB  (X converted to tf32 bits)
__device__ float g_Wt[4 * N3H * 1024];       // 24 MiB  (transposed+tf32 weights, [N,K])

// ---------------------------------------------------------------------------
// helpers
// ---------------------------------------------------------------------------
__device__ __forceinline__ float to_tf32(float x) {
    uint32_t u;
    asm("cvt.rna.tf32.f32 %0, %1;" : "=r"(u) : "f"(x));
    return __uint_as_float(u);
}

__device__ __forceinline__ void cp16(void* s, const void* g) {
    uint32_t sa = (uint32_t)__cvta_generic_to_shared(s);
    asm volatile("cp.async.cg.shared.global [%0], [%1], 16;" :: "r"(sa), "l"(g));
}

__device__ __forceinline__ void mma_tf32(float* c, const uint32_t* a, const uint32_t* b) {
    asm volatile(
        "mma.sync.aligned.m16n8k8.row.col.f32.tf32.tf32.f32 "
        "{%0,%1,%2,%3}, {%4,%5,%6,%7}, {%8,%9}, {%0,%1,%2,%3};"
        : "+f"(c[0]), "+f"(c[1]), "+f"(c[2]), "+f"(c[3])
        : "r"(a[0]), "r"(a[1]), "r"(a[2]), "r"(a[3]), "r"(b[0]), "r"(b[1]));
}

// ---------------------------------------------------------------------------
// Transpose + tf32-convert a weight matrix: W [K, 1536] -> Wt [1536, K]
// ---------------------------------------------------------------------------
__global__ void transpose_cvt_kernel(const float* __restrict__ W,
                                     float* __restrict__ Wt, int K)
{
    __shared__ float tile[32][33];
    const int kb = blockIdx.x * 32;
    const int nb = blockIdx.y * 32;
    const int tx = threadIdx.x, ty = threadIdx.y;  // 32 x 8
#pragma unroll
    for (int r = 0; r < 32; r += 8)
        tile[ty + r][tx] = W[(size_t)(kb + ty + r) * N3H + nb + tx];
    __syncthreads();
#pragma unroll
    for (int r = 0; r < 32; r += 8)
        Wt[(size_t)(nb + ty + r) * K + kb + tx] = to_tf32(tile[tx][ty + r]);
}

// ---------------------------------------------------------------------------
// Elementwise tf32 convert: X -> Xc
// ---------------------------------------------------------------------------
__global__ void cvt_tf32_kernel(const float* __restrict__ in, float* __restrict__ out, int n4)
{
    int i = blockIdx.x * blockDim.x + threadIdx.x;
    if (i < n4) {
        float4 v = ((const float4*)in)[i];
        v.x = to_tf32(v.x); v.y = to_tf32(v.y); v.z = to_tf32(v.z); v.w = to_tf32(v.w);
        ((float4*)out)[i] = v;
    }
}

// ---------------------------------------------------------------------------
// TF32 tensor-core GEMM + bias + activation:
//   C[M, 1536] = act( A[M,K] @ Wt[1536,K]^T + bias )
// A, Wt already hold tf32 bit patterns. 128x128x32 tiles, cp.async 2-stage,
// 8 warps (2M x 4N), m16n8k8 tf32 MMA, XOR-swizzled smem (conflict-free).
// ---------------------------------------------------------------------------
template <int K>
__global__ void __launch_bounds__(256, 2) gemm_tf32_kernel(
    const float* __restrict__ A,
    const float* __restrict__ Bt,     // [1536, K]
    const float* __restrict__ bias,
    float* __restrict__ C)
{
    extern __shared__ float smem[];
    float* As = smem;                 // [2][BM*BK]
    float* Bs = smem + 2 * BM * BK;   // [2][BN*BK]

    const int tid = threadIdx.x;
    const int warp = tid >> 5;
    const int lane = tid & 31;
    const int g = lane >> 2;          // 0..7
    const int t = lane & 3;           // 0..3
    const int wm = warp & 1;          // 2 warps M
    const int wn = warp >> 1;         // 4 warps N
    const int blockM = blockIdx.y * BM;
    const int blockN = blockIdx.x * BN;

    float acc[4][4][4];
#pragma unroll
    for (int i = 0; i < 4; i++)
#pragma unroll
        for (int j = 0; j < 4; j++)
#pragma unroll
            for (int q = 0; q < 4; q++) acc[i][j][q] = 0.0f;

    // stage loader: 128 rows x 8 float4 per operand
    auto load_stage = [&](int buf, int k0) {
#pragma unroll
        for (int it = 0; it < 4; it++) {
            const int idx = tid + it * 256;
            const int row = idx >> 3;
            const int c4  = idx & 7;
            const int scol = (c4 * 4) ^ ((row * 4) & 31);
            cp16(&As[buf * BM * BK + row * BK + scol],
                 &A[(size_t)(blockM + row) * K + k0 + c4 * 4]);
            cp16(&Bs[buf * BM * BK + row * BK + scol],
                 &Bt[(size_t)(blockN + row) * K + k0 + c4 * 4]);
        }
        asm volatile("cp.async.commit_group;");
    };

    const int ntiles = K / BK;
    load_stage(0, 0);

    for (int kt = 0; kt < ntiles; kt++) {
        if (kt + 1 < ntiles) {
            load_stage((kt + 1) & 1, (kt + 1) * BK);
            asm volatile("cp.async.wait_group 1;");
        } else {
            asm volatile("cp.async.wait_group 0;");
        }
        __syncthreads();

        const float* Ab = &As[(kt & 1) * BM * BK];
        const float* Bb = &Bs[(kt & 1) * BM * BK];

#pragma unroll
        for (int kk = 0; kk < BK; kk += 8) {
            uint32_t af[4][4], bf[4][2];
#pragma unroll
            for (int i = 0; i < 4; i++) {
                const int m0 = wm * 64 + i * 16 + g;
                const int m1 = m0 + 8;
                const int s0 = (m0 * 4) & 31;
                const int s1 = (m1 * 4) & 31;
                af[i][0] = __float_as_uint(Ab[m0 * BK + ((kk + t) ^ s0)]);
                af[i][1] = __float_as_uint(Ab[m1 * BK + ((kk + t) ^ s1)]);
                af[i][2] = __float_as_uint(Ab[m0 * BK + ((kk + t + 4) ^ s0)]);
                af[i][3] = __float_as_uint(Ab[m1 * BK + ((kk + t + 4) ^ s1)]);
            }
#pragma unroll
            for (int j = 0; j < 4; j++) {
                const int n0 = wn * 32 + j * 8 + g;
                const int s0 = (n0 * 4) & 31;
                bf[j][0] = __float_as_uint(Bb[n0 * BK + ((kk + t) ^ s0)]);
                bf[j][1] = __float_as_uint(Bb[n0 * BK + ((kk + t + 4) ^ s0)]);
            }
#pragma unroll
            for (int i = 0; i < 4; i++)
#pragma unroll
                for (int j = 0; j < 4; j++)
                    mma_tf32(acc[i][j], af[i], bf[j]);
        }
        __syncthreads();
    }

    // Epilogue: bias + activation. Region boundary (col 512) is block-uniform.
    const bool is_tanh = (blockN < HH);
#pragma unroll
    for (int i = 0; i < 4; i++) {
        const int row0 = blockM + wm * 64 + i * 16 + g;
#pragma unroll
        for (int j = 0; j < 4; j++) {
            const int col = blockN + wn * 32 + j * 8 + 2 * t;
            const float b0 = bias[col], b1 = bias[col + 1];
            float v[4] = {acc[i][j][0] + b0, acc[i][j][1] + b1,
                          acc[i][j][2] + b0, acc[i][j][3] + b1};
            if (is_tanh) {
#pragma unroll
                for (int q = 0; q < 4; q++) v[q] = tanhf(v[q]);
            } else {
#pragma unroll
                for (int q = 0; q < 4; q++) v[q] = 1.0f / (1.0f + __expf(-v[q]));
            }
            *(float2*)&C[(size_t)row0 * N3H + col]       = make_float2(v[0], v[1]);
            *(float2*)&C[(size_t)(row0 + 8) * N3H + col] = make_float2(v[2], v[3]);
        }
    }
}

// ---------------------------------------------------------------------------
// fo-pooling scan, both directions in one launch.
// One thread per (dir, b, h). CVT: convert output to tf32 bits (layer-1 ->
// feeds the next tf32 GEMM for free).
// ---------------------------------------------------------------------------
template <bool CVT>
__global__ void __launch_bounds__(256) scan_kernel(
    const float* __restrict__ ZFOf,
    const float* __restrict__ ZFOb,
    float* __restrict__ Y)
{
    const int tt  = blockIdx.x * blockDim.x + threadIdx.x;  // 0..16383
    const int dir = tt >> 13;
    const int b   = (tt >> 9) & 15;
    const int h   = tt & 511;

    const float* __restrict__ Z = dir ? ZFOb : ZFOf;
    const size_t rowBase = (size_t)b * SS;
    const int outOff = dir * HH + h;

    float c = 0.0f;
    constexpr int CH = 8;
    for (int sc = 0; sc < SS; sc += CH) {
        float zv[CH], fv[CH], ov[CH];
#pragma unroll
        for (int j = 0; j < CH; j++) {
            const int s = dir ? (SS - 1 - (sc + j)) : (sc + j);
            const size_t idx = (rowBase + s) * N3H + h;
            zv[j] = Z[idx];
            fv[j] = Z[idx + 512];
            ov[j] = Z[idx + 1024];
        }
#pragma unroll
        for (int j = 0; j < CH; j++) {
            c = fv[j] * c + (1.0f - fv[j]) * zv[j];
            const int s = dir ? (SS - 1 - (sc + j)) : (sc + j);
            float out = ov[j] * c;
            if (CVT) out = to_tf32(out);
            Y[(rowBase + s) * OUTC + outOff] = out;
        }
    }
}

// ---------------------------------------------------------------------------
extern "C" void kernel_launch(void* const* d_in, const int* in_sizes, int n_in,
                              void* d_out, int out_size)
{
    const float* X     = (const float*)d_in[0];
    // d_in[1] = seqlens (unused, per reference)
    const float* W_fw0 = (const float*)d_in[2];
    const float* b_fw0 = (const float*)d_in[3];
    const float* W_bw0 = (const float*)d_in[4];
    const float* b_bw0 = (const float*)d_in[5];
    const float* W_fw1 = (const float*)d_in[6];
    const float* b_fw1 = (const float*)d_in[7];
    const float* W_bw1 = (const float*)d_in[8];
    const float* b_bw1 = (const float*)d_in[9];
    float* out = (float*)d_out;

    float *ZFOf, *ZFOb, *Y1, *Xc, *Wt;
    cudaGetSymbolAddress((void**)&ZFOf, g_ZFO_f);
    cudaGetSymbolAddress((void**)&ZFOb, g_ZFO_b);
    cudaGetSymbolAddress((void**)&Y1,  g_Y1);
    cudaGetSymbolAddress((void**)&Xc,  g_Xc);
    cudaGetSymbolAddress((void**)&Wt,  g_Wt);

    float* Wt0f = Wt;
    float* Wt0b = Wt + (size_t)N3H * 1024;
    float* Wt1f = Wt + (size_t)N3H * 1024 * 2;
    float* Wt1b = Wt + (size_t)N3H * 1024 * 3;

    const int smemBytes = 2 * (BM + BN) * BK * sizeof(float);  // 64 KiB
    cudaFuncSetAttribute(gemm_tf32_kernel<DD>,
                         cudaFuncAttributeMaxDynamicSharedMemorySize, smemBytes);
    cudaFuncSetAttribute(gemm_tf32_kernel<OUTC>,
                         cudaFuncAttributeMaxDynamicSharedMemorySize, smemBytes);

    // Pre-pass: transpose+tf32 weights, tf32-convert X
    {
        dim3 blk(32, 8);
        transpose_cvt_kernel<<<dim3(DD / 32,  N3H / 32), blk>>>(W_fw0, Wt0f, DD);
        transpose_cvt_kernel<<<dim3(DD / 32,  N3H / 32), blk>>>(W_bw0, Wt0b, DD);
        transpose_cvt_kernel<<<dim3(OUTC / 32, N3H / 32), blk>>>(W_fw1, Wt1f, OUTC);
        transpose_cvt_kernel<<<dim3(OUTC / 32, N3H / 32), blk>>>(W_bw1, Wt1b, OUTC);
        const int n4 = MM * DD / 4;
        cvt_tf32_kernel<<<(n4 + 255) / 256, 256>>>(X, Xc, n4);
    }

    dim3 gemmGrid(N3H / BN, MM / BM);   // 12 x 256
    dim3 gemmBlock(256);
    dim3 scanGrid(16384 / 256);
    dim3 scanBlock(256);

    // Layer 0
    gemm_tf32_kernel<DD><<<gemmGrid, gemmBlock, smemBytes>>>(Xc, Wt0f, b_fw0, ZFOf);
    gemm_tf32_kernel<DD><<<gemmGrid, gemmBlock, smemBytes>>>(Xc, Wt0b, b_bw0, ZFOb);
    scan_kernel<true><<<scanGrid, scanBlock>>>(ZFOf, ZFOb, Y1);

    // Layer 1
    gemm_tf32_kernel<OUTC><<<gemmGrid, gemmBlock, smemBytes>>>(Y1, Wt1f, b_fw1, ZFOf);
    gemm_tf32_kernel<OUTC><<<gemmGrid, gemmBlock, smemBytes>>>(Y1, Wt1b, b_bw1, ZFOb);
    scan_kernel<false><<<scanGrid, scanBlock>>>(ZFOf, ZFOb, out);
}